// round 4
// baseline (speedup 1.0000x reference)
#include <cuda_runtime.h>
#include <cuda_bf16.h>

#define NEG_INF -1e10f
#define TMN 64        // nodes per block
#define HS  132       // smem row stride (floats), %4==0 for float4, pad breaks conflicts

// Fused: masked neighbor max-pool (1 warp/node) -> smem H -> block-local GEMM
// out[:,0:128]   = relu(self)
// out[:,128:256] = relu(H @ W)
__global__ __launch_bounds__(256, 4)
void fused_kernel(const float* __restrict__ self_vecs,   // [N,128]
                  const float* __restrict__ neigh,       // [N,32,128]
                  const int*   __restrict__ mask,        // [N,32]
                  const float* __restrict__ W,           // [128,128]
                  float*       __restrict__ out,         // [N,256]
                  int N)
{
    __shared__ float Hs[TMN * HS];

    const int tid  = threadIdx.x;
    const int lane = tid & 31;
    const int warp = tid >> 5;              // 0..7
    const int n0   = blockIdx.x * TMN;

    // ---------------- Phase 1: pool 8 nodes per warp ----------------
    #pragma unroll 1
    for (int i = 0; i < 8; i++) {
        const int ln = warp * 8 + i;
        const int n  = n0 + ln;
        if (n < N) {
            // one mask element per lane -> ballot = validity bitmask
            const int mv = mask[n * 32 + lane];
            const unsigned vm = __ballot_sync(0xffffffffu, mv > 0);

            float4 m = make_float4(NEG_INF, NEG_INF, NEG_INF, NEG_INF);
            const float4* np = reinterpret_cast<const float4*>(neigh + (size_t)n * 32 * 128) + lane;
            #pragma unroll
            for (int k = 0; k < 32; k++) {
                if ((vm >> k) & 1u) {
                    float4 v = np[(size_t)k * 32];
                    m.x = fmaxf(m.x, v.x);
                    m.y = fmaxf(m.y, v.y);
                    m.z = fmaxf(m.z, v.z);
                    m.w = fmaxf(m.w, v.w);
                }
            }
            reinterpret_cast<float4*>(Hs + ln * HS)[lane] = m;

            // fused self path: relu(self) -> out[:, 0:128]
            float4 s = reinterpret_cast<const float4*>(self_vecs + (size_t)n * 128)[lane];
            s.x = fmaxf(s.x, 0.f); s.y = fmaxf(s.y, 0.f);
            s.z = fmaxf(s.z, 0.f); s.w = fmaxf(s.w, 0.f);
            reinterpret_cast<float4*>(out + (size_t)n * 256)[lane] = s;
        } else {
            reinterpret_cast<float4*>(Hs + ln * HS)[lane] =
                make_float4(0.f, 0.f, 0.f, 0.f);
        }
    }
    __syncthreads();

    // ---------------- Phase 2: C[64x128] = Hs @ W, 4x8 micro-tile ----------------
    const int tx = tid & 15;      // 0..15 -> 8 output cols each
    const int ty = tid >> 4;      // 0..15 -> 4 node rows each

    float acc[4][8];
    #pragma unroll
    for (int i = 0; i < 4; i++)
        #pragma unroll
        for (int j = 0; j < 8; j++)
            acc[i][j] = 0.f;

    const float* wbase = W + tx * 8;

    #pragma unroll 4
    for (int kk = 0; kk < 128; kk++) {
        float a[4];
        #pragma unroll
        for (int i = 0; i < 4; i++)
            a[i] = Hs[(ty * 4 + i) * HS + kk];     // broadcast LDS, conflict-free

        const float4 b0 = __ldg(reinterpret_cast<const float4*>(wbase + kk * 128));
        const float4 b1 = __ldg(reinterpret_cast<const float4*>(wbase + kk * 128 + 4));

        #pragma unroll
        for (int i = 0; i < 4; i++) {
            acc[i][0] = fmaf(a[i], b0.x, acc[i][0]);
            acc[i][1] = fmaf(a[i], b0.y, acc[i][1]);
            acc[i][2] = fmaf(a[i], b0.z, acc[i][2]);
            acc[i][3] = fmaf(a[i], b0.w, acc[i][3]);
            acc[i][4] = fmaf(a[i], b1.x, acc[i][4]);
            acc[i][5] = fmaf(a[i], b1.y, acc[i][5]);
            acc[i][6] = fmaf(a[i], b1.z, acc[i][6]);
            acc[i][7] = fmaf(a[i], b1.w, acc[i][7]);
        }
    }

    // relu + store neighbor half
    #pragma unroll
    for (int i = 0; i < 4; i++) {
        const int n = n0 + ty * 4 + i;
        if (n < N) {
            float4 c0, c1;
            c0.x = fmaxf(acc[i][0], 0.f); c0.y = fmaxf(acc[i][1], 0.f);
            c0.z = fmaxf(acc[i][2], 0.f); c0.w = fmaxf(acc[i][3], 0.f);
            c1.x = fmaxf(acc[i][4], 0.f); c1.y = fmaxf(acc[i][5], 0.f);
            c1.z = fmaxf(acc[i][6], 0.f); c1.w = fmaxf(acc[i][7], 0.f);
            float* op = out + (size_t)n * 256 + 128 + tx * 8;
            reinterpret_cast<float4*>(op)[0] = c0;
            reinterpret_cast<float4*>(op)[1] = c1;
        }
    }
}

extern "C" void kernel_launch(void* const* d_in, const int* in_sizes, int n_in,
                              void* d_out, int out_size)
{
    const float* self_vecs = (const float*)d_in[0];   // [N,128]
    const float* neigh     = (const float*)d_in[1];   // [N,32,128]
    const int*   mask      = (const int*)  d_in[2];   // [N,32]
    const float* W         = (const float*)d_in[3];   // [128,128]
    float* out = (float*)d_out;                        // [N,256]

    const int N = in_sizes[0] / 128;
    const int grid = (N + TMN - 1) / TMN;
    fused_kernel<<<grid, 256>>>(self_vecs, neigh, mask, W, out, N);
}